// round 9
// baseline (speedup 1.0000x reference)
#include <cuda_runtime.h>
#include <cuda_fp16.h>
#include <cstdint>

// Shapes
#define NB 256
#define NF 8
#define NS 200
#define ND 64
#define NH 36
#define NBF (NB*NF)          // 2048
#define NSTAT (NF*NH)        // 288
#define EPS_V 1e-3f

#define NTILES 400           // tiles of 128 rows over NB*NS=51200 rows per f
#define P1T 128
#define P1GRID (NF*NTILES)   // 3200

// ---- pass1 shared memory (float indices) ----
// A_s:   [0,3072)       [k=64][quarter=4][12] (cols 9..11 of each quarter zero)
// qh_s:  [3072,3152)    [2][40]
// sp_s:  [3152,3312)    partials
// kt:    [3328,11584)   key transposed [k=64][129]; reused as h staging [128][38]
#define SM_A 0
#define SM_QH 3072
#define SM_SP 3152
#define SM_KT 3328
#define KTP 129
#define HPAD 38
#define P1_SMEM_FLOATS (SM_KT + ND*KTP)            // 11584
#define P1_SMEM_BYTES  (P1_SMEM_FLOATS*4)          // 46336

// Scratch (no allocs -> device globals)
__device__ __half2 g_h[(size_t)NBF * (NS * NH / 2)];   // fp16 hidden acts
__device__ float g_psum[P1GRID * NH];
__device__ float g_psq [P1GRID * NH];
__device__ float g_mean[NSTAT];
__device__ float g_inv [NSTAT];

union F4U2 { float4 f4; ulonglong2 u2; };
union F2U1 { float2 f2; unsigned long long u; };

__device__ __forceinline__ unsigned long long pack2(float x) {
    unsigned long long r;
    asm("mov.b64 %0, {%1, %1};" : "=l"(r) : "f"(x));
    return r;
}
__device__ __forceinline__ void fma2(unsigned long long &acc,
                                     unsigned long long a,
                                     unsigned long long b) {
    asm("fma.rn.f32x2 %0, %1, %2, %0;" : "+l"(acc) : "l"(a), "l"(b));
}

// FFMA-only sigmoid (no MUFU pressure)
__device__ __forceinline__ float fast_sigmoid(float z) {
    float x = -z * 1.4426950408889634f;
    x = fminf(fmaxf(x, -30.0f), 30.0f);
    float n = rintf(x);
    float fr = x - n;
    float p = 0.0013333558f;
    p = fmaf(p, fr, 0.009618129f);
    p = fmaf(p, fr, 0.055504109f);
    p = fmaf(p, fr, 0.24022651f);
    p = fmaf(p, fr, 0.69314718f);
    p = fmaf(p, fr, 1.0f);
    float sc = __int_as_float(((int)n + 127) << 23);
    float e = p * sc;                 // exp(-z)
    float w = 1.0f + e;
    float r = __int_as_float(0x7EF311C3 - __float_as_int(w));
    r = r * (2.0f - w * r);
    r = r * (2.0f - w * r);
    return r;
}

// ---------------------------------------------------------------------------
// Pass 1: per-CTA 128-row tile of K_f @ A_f. h = key@A + qh[b].
// Warp = 9-col quarter; lane = 4 rows {l,l+32,l+64,l+96}.
// Per k per warp: 3 A-broadcast LDS + 4 conflict-free key LDS -> 20 fma-instr.
// ---------------------------------------------------------------------------
__global__ void __launch_bounds__(P1T, 4) pass1_kernel(
    const float* __restrict__ q, const float* __restrict__ key,
    const float* __restrict__ W_h, const float* __restrict__ b_h)
{
    extern __shared__ float sm[];
    float* A_s   = sm + SM_A;     // [64][48]
    float* qh_sm = sm + SM_QH;    // [2][40]
    float* sp_s  = sm + SM_SP;
    float* kt    = sm + SM_KT;    // [64][129]
    float* h_st  = sm + SM_KT;    // reuse: [128][38]

    const int t = threadIdx.x;
    const int wq = t >> 5;        // warp = col quarter (cols 9*wq .. 9*wq+8)
    const int l  = t & 31;        // rows l, l+32, l+64, l+96
    const int f    = blockIdx.x / NTILES;
    const int tile = blockIdx.x - f * NTILES;
    const int g0 = tile * 128;
    const int b0 = g0 / NS;
    const float* Wf = W_h + f * (3 * ND * NH);

    // A_s[k][qq*12 + cc] = W_k - W_d (cc<9), zero pad
    #pragma unroll
    for (int it = 0; it < 24; ++it) {
        int i = t + it * P1T;            // 0..3071
        int k = i / 48, c = i - k * 48;
        int qq = c / 12, cc = c - qq * 12;
        float v = 0.0f;
        if (cc < 9) {
            int j = qq * 9 + cc;
            v = Wf[k * NH + j] - Wf[(2 * ND + k) * NH + j];
        }
        A_s[i] = v;
    }

    // key tile -> transposed smem kt[k][row] (coalesced LDG.128, scalar STS)
    const float4* kg = (const float4*)key;
    #pragma unroll
    for (int it = 0; it < 16; ++it) {
        int i = t + it * P1T;            // 0..2047
        int row = i >> 4, c4 = (i & 15) * 4;
        int g = g0 + row;
        int b = g / NS, s = g - b * NS;
        float4 v = kg[((size_t)(b * NF + f) * NS + s) * 16 + (i & 15)];
        kt[(c4 + 0) * KTP + row] = v.x;
        kt[(c4 + 1) * KTP + row] = v.y;
        kt[(c4 + 2) * KTP + row] = v.z;
        kt[(c4 + 3) * KTP + row] = v.w;
    }

    // qh: 72 threads = (bb:2) x (j:36), full 64-k dot each
    if (t < 72) {
        int bb = t / 36, j = t - bb * 36;
        int b = b0 + bb; if (b > NB - 1) b = NB - 1;
        const float* qr = q + (size_t)(b * NF + f) * ND;
        float s = b_h[f * NH + j];
        #pragma unroll 4
        for (int k = 0; k < ND; ++k)
            s += qr[k] * (Wf[(ND + k) * NH + j] + Wf[(2 * ND + k) * NH + j]);
        qh_sm[bb * 40 + j] = s;
    }
    __syncthreads();

    // ---- main GEMM ----
    unsigned long long acc[4][4];
    float acc8[4];
    #pragma unroll
    for (int j4 = 0; j4 < 4; ++j4) {
        acc8[j4] = 0.0f;
        #pragma unroll
        for (int c = 0; c < 4; ++c) acc[j4][c] = 0ull;
    }

    const float* abase = A_s + wq * 12;
    const float* kbase = kt + l;
    #pragma unroll 4
    for (int k = 0; k < ND; ++k) {
        const float* ar = abase + k * 48;
        F4U2 u0; u0.f4 = *(const float4*)(ar);       // a0..a3
        F4U2 u1; u1.f4 = *(const float4*)(ar + 4);   // a4..a7
        float a8 = ar[8];
        const float* kc = kbase + k * KTP;
        float kv0 = kc[0], kv1 = kc[32], kv2 = kc[64], kv3 = kc[96];
        {
            unsigned long long kk = pack2(kv0);
            fma2(acc[0][0], u0.u2.x, kk); fma2(acc[0][1], u0.u2.y, kk);
            fma2(acc[0][2], u1.u2.x, kk); fma2(acc[0][3], u1.u2.y, kk);
            acc8[0] = fmaf(a8, kv0, acc8[0]);
        }
        {
            unsigned long long kk = pack2(kv1);
            fma2(acc[1][0], u0.u2.x, kk); fma2(acc[1][1], u0.u2.y, kk);
            fma2(acc[1][2], u1.u2.x, kk); fma2(acc[1][3], u1.u2.y, kk);
            acc8[1] = fmaf(a8, kv1, acc8[1]);
        }
        {
            unsigned long long kk = pack2(kv2);
            fma2(acc[2][0], u0.u2.x, kk); fma2(acc[2][1], u0.u2.y, kk);
            fma2(acc[2][2], u1.u2.x, kk); fma2(acc[2][3], u1.u2.y, kk);
            acc8[2] = fmaf(a8, kv2, acc8[2]);
        }
        {
            unsigned long long kk = pack2(kv3);
            fma2(acc[3][0], u0.u2.x, kk); fma2(acc[3][1], u0.u2.y, kk);
            fma2(acc[3][2], u1.u2.x, kk); fma2(acc[3][3], u1.u2.y, kk);
            acc8[3] = fmaf(a8, kv3, acc8[3]);
        }
    }
    __syncthreads();   // done reading kt -> safe to overwrite with h

    // epilogue: h = acc + qh[bsel(row)]
    const int jc = wq * 9;
    #pragma unroll
    for (int j4 = 0; j4 < 4; ++j4) {
        int r = l + 32 * j4;
        int bsel = ((g0 + r) >= (b0 + 1) * NS) ? 1 : 0;
        const float* qh = qh_sm + bsel * 40 + jc;
        float* hr = h_st + r * HPAD + jc;
        F2U1 u;
        u.u = acc[j4][0]; hr[0] = u.f2.x + qh[0]; hr[1] = u.f2.y + qh[1];
        u.u = acc[j4][1]; hr[2] = u.f2.x + qh[2]; hr[3] = u.f2.y + qh[3];
        u.u = acc[j4][2]; hr[4] = u.f2.x + qh[4]; hr[5] = u.f2.y + qh[5];
        u.u = acc[j4][3]; hr[6] = u.f2.x + qh[6]; hr[7] = u.f2.y + qh[7];
        hr[8] = acc8[j4] + qh[8];
    }
    __syncthreads();

    // fp16 copy-out: 2304 half2 over 128 threads
    #pragma unroll
    for (int it = 0; it < 18; ++it) {
        int i = t + it * P1T;           // 0..2303
        int row = i / 18, e = i - row * 18;
        int gg = g0 + row;
        int b = gg / NS, s = gg - b * NS;
        float2 v = *(const float2*)(h_st + row * HPAD + 2 * e);
        g_h[((size_t)(b * NF + f) * NS + s) * 18 + e] = __float22half2_rn(v);
    }
    // per-CTA stat partials: 72 threads = (j:36) x (c:2 chunks of 64 rows)
    if (t < 72) {
        int j = t >> 1, c = t & 1;
        float ss = 0.f, qq = 0.f;
        #pragma unroll 4
        for (int rr = c * 64; rr < c * 64 + 64; ++rr) {
            float v = h_st[rr * HPAD + j];
            ss += v; qq += v * v;
        }
        sp_s[t] = ss;
        sp_s[72 + t] = qq;
    }
    __syncthreads();
    if (t < NH) {
        float ss = sp_s[t*2] + sp_s[t*2+1];
        float qq = sp_s[72 + t*2] + sp_s[72 + t*2+1];
        g_psum[blockIdx.x * NH + t] = ss;
        g_psq [blockIdx.x * NH + t] = qq;
    }
}

// ---------------------------------------------------------------------------
// Stats finalize: reduce 400 tile-partials per (f,j)
// ---------------------------------------------------------------------------
__global__ void __launch_bounds__(256) kstats_kernel()
{
    __shared__ float rs[256], rq[256];
    const int col = blockIdx.x;           // f*36 + j
    const int f = col / NH, j = col - f * NH;
    const int t = threadIdx.x;
    float ss = 0.f, qq = 0.f;
    for (int i = t; i < NTILES; i += 256) {
        ss += g_psum[(f * NTILES + i) * NH + j];
        qq += g_psq [(f * NTILES + i) * NH + j];
    }
    rs[t] = ss; rq[t] = qq;
    __syncthreads();
    for (int off = 128; off > 0; off >>= 1) {
        if (t < off) { rs[t] += rs[t + off]; rq[t] += rq[t + off]; }
        __syncthreads();
    }
    if (t == 0) {
        const float invN = 1.0f / (float)(NB * NS);
        float mean = rs[0] * invN;
        float var  = rq[0] * invN - mean * mean;
        g_mean[col] = mean;
        g_inv[col]  = rsqrtf(var + EPS_V);
    }
}

// ---------------------------------------------------------------------------
// Pass 3: gate + scores + masked softmax + attn @ key. One block per (b,f).
// ---------------------------------------------------------------------------
__global__ void __launch_bounds__(256) pass3_kernel(
    const float* __restrict__ key, const float* __restrict__ alpha,
    const float* __restrict__ W_o, const float* __restrict__ b_o,
    const int* __restrict__ seqnum, float* __restrict__ out)
{
    __shared__ float h_sm[NS * NH];
    __shared__ float inv_s[NH], nm_s[NH], wo_s[NH];
    __shared__ float sc[NS];
    __shared__ float red[256];
    __shared__ float opart[256];

    const int tid = threadIdx.x;
    const int bf  = blockIdx.x;
    const int f   = bf & 7;
    const int n   = seqnum[bf];

    {
        const __half2* hg = g_h + (size_t)bf * (NS * NH / 2);
        for (int i = tid; i < NS * NH / 2; i += 256)
            ((float2*)h_sm)[i] = __half22float2(hg[i]);
    }
    if (tid < NH) {
        float m  = g_mean[f * NH + tid];
        float iv = g_inv [f * NH + tid];
        inv_s[tid] = iv;
        nm_s[tid]  = -m * iv;
        wo_s[tid]  = W_o[f * NH + tid];
    }
    const float al  = alpha[f];
    const float oma = 1.0f - al;
    __syncthreads();

    float score = -3.0e38f;
    if (tid < n) {
        float s = b_o[f];
        const float* hr = h_sm + tid * NH;
        #pragma unroll 6
        for (int j = 0; j < NH; ++j) {
            float v = hr[j];
            float z = fmaf(v, inv_s[j], nm_s[j]);
            float p = fast_sigmoid(z);
            float g = fmaf(oma, p, al) * v;
            s = fmaf(g, wo_s[j], s);
        }
        score = s;
    }
    red[tid] = score;
    __syncthreads();
    for (int off = 128; off > 0; off >>= 1) {
        if (tid < off) red[tid] = fmaxf(red[tid], red[tid + off]);
        __syncthreads();
    }
    const float mx = red[0];
    __syncthreads();
    float e = 0.0f;
    if (tid < n) {
        e = __expf(score - mx);
        sc[tid] = e;
    }
    red[tid] = e;
    __syncthreads();
    for (int off = 128; off > 0; off >>= 1) {
        if (tid < off) red[tid] += red[tid + off];
        __syncthreads();
    }
    const float denom = red[0];

    const int d = tid & 63;
    const int g = tid >> 6;
    const float* kb = key + (size_t)bf * (NS * ND);
    float a0 = 0.0f;
    for (int s = g; s < n; s += 4)
        a0 = fmaf(sc[s], kb[s * ND + d], a0);
    opart[tid] = a0;
    __syncthreads();
    if (tid < ND) {
        float o = opart[tid] + opart[tid + 64] + opart[tid + 128] + opart[tid + 192];
        out[(size_t)bf * ND + tid] = o / denom;
    }
}

// ---------------------------------------------------------------------------
extern "C" void kernel_launch(void* const* d_in, const int* in_sizes, int n_in,
                              void* d_out, int out_size)
{
    const float* q      = (const float*)d_in[0];
    const float* key    = (const float*)d_in[1];
    const float* W_h    = (const float*)d_in[2];
    const float* b_h    = (const float*)d_in[3];
    const float* alpha  = (const float*)d_in[4];
    const float* W_o    = (const float*)d_in[5];
    const float* b_o    = (const float*)d_in[6];
    const int*   seqn   = (const int*)d_in[7];
    float* out = (float*)d_out;

    cudaFuncSetAttribute(pass1_kernel,
                         cudaFuncAttributeMaxDynamicSharedMemorySize,
                         P1_SMEM_BYTES);

    pass1_kernel<<<P1GRID, P1T, P1_SMEM_BYTES>>>(q, key, W_h, b_h);
    kstats_kernel<<<NSTAT, 256>>>();
    pass3_kernel<<<NBF, 256>>>(key, alpha, W_o, b_o, seqn, out);
}

// round 10
// speedup vs baseline: 1.0045x; 1.0045x over previous
#include <cuda_runtime.h>
#include <cuda_fp16.h>
#include <cstdint>

// Shapes
#define NB 256
#define NF 8
#define NS 200
#define ND 64
#define NH 36
#define NBF (NB*NF)          // 2048
#define NSTAT (NF*NH)        // 288
#define EPS_V 1e-3f

#define NTILES 400           // tiles of 128 rows over NB*NS=51200 rows per f
#define P1T 128
#define P1GRID (NF*NTILES)   // 3200

// ---- pass1 shared memory (float indices) ----
// A_s:   [0,3072)       [k=64][quarter=4][12] (cols 9..11 zero)
// qh_s:  [3072,3152)    [2][40]
// sp_s:  [3152,3312)    partials
// kt:    [3328,7552)    key fp16 [k=64][132 halves] (interleaved rows j/j+64)
// h_st:  [3328,8192)    reuse: h staging [128][38] f32
#define SM_A 0
#define SM_QH 3072
#define SM_SP 3152
#define SM_KT 3328
#define KTH 132               // halves per k row
#define HPAD 38
#define P1_SMEM_FLOATS 8192
#define P1_SMEM_BYTES  (P1_SMEM_FLOATS*4)          // 32768

// Scratch (no allocs -> device globals)
__device__ __half2 g_h[(size_t)NBF * (NS * NH / 2)];   // fp16 hidden acts
__device__ float g_psum[P1GRID * NH];
__device__ float g_psq [P1GRID * NH];
__device__ float g_mean[NSTAT];
__device__ float g_inv [NSTAT];

union F4U2 { float4 f4; ulonglong2 u2; };
union F2U1 { float2 f2; unsigned long long u; };

__device__ __forceinline__ unsigned long long pack2(float x) {
    unsigned long long r;
    asm("mov.b64 %0, {%1, %1};" : "=l"(r) : "f"(x));
    return r;
}
__device__ __forceinline__ void fma2(unsigned long long &acc,
                                     unsigned long long a,
                                     unsigned long long b) {
    asm("fma.rn.f32x2 %0, %1, %2, %0;" : "+l"(acc) : "l"(a), "l"(b));
}

// FFMA-only sigmoid (no MUFU pressure)
__device__ __forceinline__ float fast_sigmoid(float z) {
    float x = -z * 1.4426950408889634f;
    x = fminf(fmaxf(x, -30.0f), 30.0f);
    float n = rintf(x);
    float fr = x - n;
    float p = 0.0013333558f;
    p = fmaf(p, fr, 0.009618129f);
    p = fmaf(p, fr, 0.055504109f);
    p = fmaf(p, fr, 0.24022651f);
    p = fmaf(p, fr, 0.69314718f);
    p = fmaf(p, fr, 1.0f);
    float sc = __int_as_float(((int)n + 127) << 23);
    float e = p * sc;                 // exp(-z)
    float w = 1.0f + e;
    float r = __int_as_float(0x7EF311C3 - __float_as_int(w));
    r = r * (2.0f - w * r);
    r = r * (2.0f - w * r);
    return r;
}

// ---------------------------------------------------------------------------
// Pass 1: per-CTA 128-row tile of K_f @ A_f. h = key@A + qh[b].
// Warp = 9-col quarter; lane = rows {l, l+32, l+64, l+96}.
// Key in smem as fp16 interleaved: kt[k][2j+sel] = key(row j+64*sel, k).
// Per k per warp: 3 A LDS (broadcast) + 2 key LDS -> 20 fma instr.
// ---------------------------------------------------------------------------
__global__ void __launch_bounds__(P1T, 6) pass1_kernel(
    const float* __restrict__ q, const float* __restrict__ key,
    const float* __restrict__ W_h, const float* __restrict__ b_h)
{
    extern __shared__ float sm[];
    float* A_s   = sm + SM_A;     // [64][48]
    float* qh_sm = sm + SM_QH;    // [2][40]
    float* sp_s  = sm + SM_SP;
    __half* kth  = (__half*)(sm + SM_KT);   // [64][132]
    float* h_st  = sm + SM_KT;    // reuse: [128][38]

    const int t = threadIdx.x;
    const int wq = t >> 5;        // warp = col quarter (cols 9*wq .. 9*wq+8)
    const int l  = t & 31;
    const int f    = blockIdx.x / NTILES;
    const int tile = blockIdx.x - f * NTILES;
    const int g0 = tile * 128;
    const int b0 = g0 / NS;
    const float* Wf = W_h + f * (3 * ND * NH);

    // A_s[k][qq*12 + cc] = W_k - W_d (cc<9), zero pad
    #pragma unroll
    for (int it = 0; it < 24; ++it) {
        int i = t + it * P1T;            // 0..3071
        int k = i / 48, c = i - k * 48;
        int qq = c / 12, cc = c - qq * 12;
        float v = 0.0f;
        if (cc < 9) {
            int j = qq * 9 + cc;
            v = Wf[k * NH + j] - Wf[(2 * ND + k) * NH + j];
        }
        A_s[i] = v;
    }

    // key tile -> fp16 interleaved transposed smem
    const float4* kg = (const float4*)key;
    #pragma unroll
    for (int it = 0; it < 16; ++it) {
        int i = t + it * P1T;            // 0..2047
        int row = i >> 4, c4 = (i & 15) * 4;
        int g = g0 + row;
        int b = g / NS, s = g - b * NS;
        float4 v = kg[((size_t)(b * NF + f) * NS + s) * 16 + (i & 15)];
        int jr = 2 * (row & 63) + (row >> 6);
        kth[(c4 + 0) * KTH + jr] = __float2half_rn(v.x);
        kth[(c4 + 1) * KTH + jr] = __float2half_rn(v.y);
        kth[(c4 + 2) * KTH + jr] = __float2half_rn(v.z);
        kth[(c4 + 3) * KTH + jr] = __float2half_rn(v.w);
    }

    // qh: 72 threads = (bb:2) x (j:36), full 64-k dot each
    if (t < 72) {
        int bb = t / 36, j = t - bb * 36;
        int b = b0 + bb; if (b > NB - 1) b = NB - 1;
        const float* qr = q + (size_t)(b * NF + f) * ND;
        float s = b_h[f * NH + j];
        #pragma unroll 4
        for (int k = 0; k < ND; ++k)
            s += qr[k] * (Wf[(ND + k) * NH + j] + Wf[(2 * ND + k) * NH + j]);
        qh_sm[bb * 40 + j] = s;
    }
    __syncthreads();

    // ---- main GEMM ----
    unsigned long long acc[4][4];   // [row-group][col-pair]
    float acc8[4];
    #pragma unroll
    for (int j4 = 0; j4 < 4; ++j4) {
        acc8[j4] = 0.0f;
        #pragma unroll
        for (int c = 0; c < 4; ++c) acc[j4][c] = 0ull;
    }

    const float* abase = A_s + wq * 12;
    const __half* kb = kth + 2 * l;
    #pragma unroll 4
    for (int k = 0; k < ND; ++k) {
        const float* ar = abase + k * 48;
        F4U2 u0; u0.f4 = *(const float4*)(ar);       // a0..a3
        F4U2 u1; u1.f4 = *(const float4*)(ar + 4);   // a4..a7
        float a8 = ar[8];
        const __half* kc = kb + k * KTH;
        __half2 kp0 = *(const __half2*)(kc);         // rows l, l+64
        __half2 kp1 = *(const __half2*)(kc + 64);    // rows l+32, l+96
        float2 v0 = __half22float2(kp0);
        float2 v1 = __half22float2(kp1);
        {
            unsigned long long kk = pack2(v0.x);      // row l -> acc[0]
            fma2(acc[0][0], u0.u2.x, kk); fma2(acc[0][1], u0.u2.y, kk);
            fma2(acc[0][2], u1.u2.x, kk); fma2(acc[0][3], u1.u2.y, kk);
            acc8[0] = fmaf(a8, v0.x, acc8[0]);
        }
        {
            unsigned long long kk = pack2(v1.x);      // row l+32 -> acc[1]
            fma2(acc[1][0], u0.u2.x, kk); fma2(acc[1][1], u0.u2.y, kk);
            fma2(acc[1][2], u1.u2.x, kk); fma2(acc[1][3], u1.u2.y, kk);
            acc8[1] = fmaf(a8, v1.x, acc8[1]);
        }
        {
            unsigned long long kk = pack2(v0.y);      // row l+64 -> acc[2]
            fma2(acc[2][0], u0.u2.x, kk); fma2(acc[2][1], u0.u2.y, kk);
            fma2(acc[2][2], u1.u2.x, kk); fma2(acc[2][3], u1.u2.y, kk);
            acc8[2] = fmaf(a8, v0.y, acc8[2]);
        }
        {
            unsigned long long kk = pack2(v1.y);      // row l+96 -> acc[3]
            fma2(acc[3][0], u0.u2.x, kk); fma2(acc[3][1], u0.u2.y, kk);
            fma2(acc[3][2], u1.u2.x, kk); fma2(acc[3][3], u1.u2.y, kk);
            acc8[3] = fmaf(a8, v1.y, acc8[3]);
        }
    }
    __syncthreads();   // done reading kt -> safe to overwrite with h

    // epilogue: h = acc + qh[bsel(row)]
    const int jc = wq * 9;
    #pragma unroll
    for (int j4 = 0; j4 < 4; ++j4) {
        int r = l + 32 * j4;
        int bsel = ((g0 + r) >= (b0 + 1) * NS) ? 1 : 0;
        const float* qh = qh_sm + bsel * 40 + jc;
        float* hr = h_st + r * HPAD + jc;
        F2U1 u;
        u.u = acc[j4][0]; hr[0] = u.f2.x + qh[0]; hr[1] = u.f2.y + qh[1];
        u.u = acc[j4][1]; hr[2] = u.f2.x + qh[2]; hr[3] = u.f2.y + qh[3];
        u.u = acc[j4][2]; hr[4] = u.f2.x + qh[4]; hr[5] = u.f2.y + qh[5];
        u.u = acc[j4][3]; hr[6] = u.f2.x + qh[6]; hr[7] = u.f2.y + qh[7];
        hr[8] = acc8[j4] + qh[8];
    }
    __syncthreads();

    // fp16 copy-out: 2304 half2 over 128 threads
    #pragma unroll
    for (int it = 0; it < 18; ++it) {
        int i = t + it * P1T;           // 0..2303
        int row = i / 18, e = i - row * 18;
        int gg = g0 + row;
        int b = gg / NS, s = gg - b * NS;
        float2 v = *(const float2*)(h_st + row * HPAD + 2 * e);
        g_h[((size_t)(b * NF + f) * NS + s) * 18 + e] = __float22half2_rn(v);
    }
    // per-CTA stat partials: 72 threads = (j:36) x (c:2 chunks of 64 rows)
    if (t < 72) {
        int j = t >> 1, c = t & 1;
        float ss = 0.f, qq = 0.f;
        #pragma unroll 4
        for (int rr = c * 64; rr < c * 64 + 64; ++rr) {
            float v = h_st[rr * HPAD + j];
            ss += v; qq += v * v;
        }
        sp_s[t] = ss;
        sp_s[72 + t] = qq;
    }
    __syncthreads();
    if (t < NH) {
        float ss = sp_s[t*2] + sp_s[t*2+1];
        float qq = sp_s[72 + t*2] + sp_s[72 + t*2+1];
        g_psum[blockIdx.x * NH + t] = ss;
        g_psq [blockIdx.x * NH + t] = qq;
    }
}

// ---------------------------------------------------------------------------
// Stats finalize: reduce 400 tile-partials per (f,j)
// ---------------------------------------------------------------------------
__global__ void __launch_bounds__(256) kstats_kernel()
{
    __shared__ float rs[256], rq[256];
    const int col = blockIdx.x;           // f*36 + j
    const int f = col / NH, j = col - f * NH;
    const int t = threadIdx.x;
    float ss = 0.f, qq = 0.f;
    for (int i = t; i < NTILES; i += 256) {
        ss += g_psum[(f * NTILES + i) * NH + j];
        qq += g_psq [(f * NTILES + i) * NH + j];
    }
    rs[t] = ss; rq[t] = qq;
    __syncthreads();
    for (int off = 128; off > 0; off >>= 1) {
        if (t < off) { rs[t] += rs[t + off]; rq[t] += rq[t + off]; }
        __syncthreads();
    }
    if (t == 0) {
        const float invN = 1.0f / (float)(NB * NS);
        float mean = rs[0] * invN;
        float var  = rq[0] * invN - mean * mean;
        g_mean[col] = mean;
        g_inv[col]  = rsqrtf(var + EPS_V);
    }
}

// ---------------------------------------------------------------------------
// Pass 3: gate + scores + masked softmax + attn @ key. One block per (b,f).
// ---------------------------------------------------------------------------
__global__ void __launch_bounds__(256) pass3_kernel(
    const float* __restrict__ key, const float* __restrict__ alpha,
    const float* __restrict__ W_o, const float* __restrict__ b_o,
    const int* __restrict__ seqnum, float* __restrict__ out)
{
    __shared__ float h_sm[NS * NH];
    __shared__ float inv_s[NH], nm_s[NH], wo_s[NH];
    __shared__ float sc[NS];
    __shared__ float red[256];
    __shared__ float opart[256];

    const int tid = threadIdx.x;
    const int bf  = blockIdx.x;
    const int f   = bf & 7;
    const int n   = seqnum[bf];

    {
        const __half2* hg = g_h + (size_t)bf * (NS * NH / 2);
        for (int i = tid; i < NS * NH / 2; i += 256)
            ((float2*)h_sm)[i] = __half22float2(hg[i]);
    }
    if (tid < NH) {
        float m  = g_mean[f * NH + tid];
        float iv = g_inv [f * NH + tid];
        inv_s[tid] = iv;
        nm_s[tid]  = -m * iv;
        wo_s[tid]  = W_o[f * NH + tid];
    }
    const float al  = alpha[f];
    const float oma = 1.0f - al;
    __syncthreads();

    float score = -3.0e38f;
    if (tid < n) {
        float s = b_o[f];
        const float* hr = h_sm + tid * NH;
        #pragma unroll 6
        for (int j = 0; j < NH; ++j) {
            float v = hr[j];
            float z = fmaf(v, inv_s[j], nm_s[j]);
            float p = fast_sigmoid(z);
            float g = fmaf(oma, p, al) * v;
            s = fmaf(g, wo_s[j], s);
        }
        score = s;
    }
    red[tid] = score;
    __syncthreads();
    for (int off = 128; off > 0; off >>= 1) {
        if (tid < off) red[tid] = fmaxf(red[tid], red[tid + off]);
        __syncthreads();
    }
    const float mx = red[0];
    __syncthreads();
    float e = 0.0f;
    if (tid < n) {
        e = __expf(score - mx);
        sc[tid] = e;
    }
    red[tid] = e;
    __syncthreads();
    for (int off = 128; off > 0; off >>= 1) {
        if (tid < off) red[tid] += red[tid + off];
        __syncthreads();
    }
    const float denom = red[0];

    const int d = tid & 63;
    const int g = tid >> 6;
    const float* kb = key + (size_t)bf * (NS * ND);
    float a0 = 0.0f;
    for (int s = g; s < n; s += 4)
        a0 = fmaf(sc[s], kb[s * ND + d], a0);
    opart[tid] = a0;
    __syncthreads();
    if (tid < ND) {
        float o = opart[tid] + opart[tid + 64] + opart[tid + 128] + opart[tid + 192];
        out[(size_t)bf * ND + tid] = o / denom;
    }
}

// ---------------------------------------------------------------------------
extern "C" void kernel_launch(void* const* d_in, const int* in_sizes, int n_in,
                              void* d_out, int out_size)
{
    const float* q      = (const float*)d_in[0];
    const float* key    = (const float*)d_in[1];
    const float* W_h    = (const float*)d_in[2];
    const float* b_h    = (const float*)d_in[3];
    const float* alpha  = (const float*)d_in[4];
    const float* W_o    = (const float*)d_in[5];
    const float* b_o    = (const float*)d_in[6];
    const int*   seqn   = (const int*)d_in[7];
    float* out = (float*)d_out;

    cudaFuncSetAttribute(pass1_kernel,
                         cudaFuncAttributeMaxDynamicSharedMemorySize,
                         P1_SMEM_BYTES);

    pass1_kernel<<<P1GRID, P1T, P1_SMEM_BYTES>>>(q, key, W_h, b_h);
    kstats_kernel<<<NSTAT, 256>>>();
    pass3_kernel<<<NBF, 256>>>(key, alpha, W_o, b_o, seqn, out);
}

// round 11
// speedup vs baseline: 1.0868x; 1.0819x over previous
#include <cuda_runtime.h>
#include <cuda_fp16.h>
#include <cstdint>

// Shapes
#define NB 256
#define NF 8
#define NS 200
#define ND 64
#define NH 36
#define NBF (NB*NF)          // 2048
#define NSTAT (NF*NH)        // 288
#define EPS_V 1e-3f

#define NTILES 400           // tiles of 128 rows over NB*NS=51200 rows per f
#define P1T 128
#define P1GRID (NF*NTILES)   // 3200

// ---- pass1 shared memory (float indices) ----
// A_s:   [0,3072)       [k=64][quarter=4][12] (cols 9..11 zero)
// qh_s:  [3072,3152)    [2][4 quarters][10]
// kt:    [3200,11456)   key f32 transposed [k=64][129]; reused as h staging [128][38]
#define SM_A 0
#define SM_QH 3072
#define SM_KT 3200
#define KTP 129
#define HPAD 38
#define P1_SMEM_FLOATS (SM_KT + ND*KTP)            // 11456
#define P1_SMEM_BYTES  (P1_SMEM_FLOATS*4)          // 45824

// Scratch (no allocs -> device globals)
__device__ __half2 g_h[(size_t)NBF * (NS * NH / 2)];   // fp16 hidden acts
__device__ float g_A  [NF * 3072];                     // prepped A, pass1 layout
__device__ float g_qh [NBF * NH];                      // prepped qh
__device__ float g_psum[P1GRID * NH];
__device__ float g_psq [P1GRID * NH];
__device__ float g_mean[NSTAT];
__device__ float g_inv [NSTAT];

union F4U2 { float4 f4; ulonglong2 u2; };
union F2U1 { float2 f2; unsigned long long u; };

__device__ __forceinline__ unsigned long long pack2(float x) {
    unsigned long long r;
    asm("mov.b64 %0, {%1, %1};" : "=l"(r) : "f"(x));
    return r;
}
__device__ __forceinline__ void fma2(unsigned long long &acc,
                                     unsigned long long a,
                                     unsigned long long b) {
    asm("fma.rn.f32x2 %0, %1, %2, %0;" : "+l"(acc) : "l"(a), "l"(b));
}

// FFMA-only sigmoid (no MUFU pressure)
__device__ __forceinline__ float fast_sigmoid(float z) {
    float x = -z * 1.4426950408889634f;
    x = fminf(fmaxf(x, -30.0f), 30.0f);
    float n = rintf(x);
    float fr = x - n;
    float p = 0.0013333558f;
    p = fmaf(p, fr, 0.009618129f);
    p = fmaf(p, fr, 0.055504109f);
    p = fmaf(p, fr, 0.24022651f);
    p = fmaf(p, fr, 0.69314718f);
    p = fmaf(p, fr, 1.0f);
    float sc = __int_as_float(((int)n + 127) << 23);
    float e = p * sc;                 // exp(-z)
    float w = 1.0f + e;
    float r = __int_as_float(0x7EF311C3 - __float_as_int(w));
    r = r * (2.0f - w * r);
    r = r * (2.0f - w * r);
    return r;
}

// ---------------------------------------------------------------------------
// Prep: A (per f) and qh (per b,f) computed ONCE instead of per pass1-CTA.
// grid = 2048 (qh blocks) + 8 (A blocks), 256 threads.
// ---------------------------------------------------------------------------
__global__ void __launch_bounds__(256) prep_kernel(
    const float* __restrict__ q, const float* __restrict__ W_h,
    const float* __restrict__ b_h)
{
    const int bid = blockIdx.x;
    const int t = threadIdx.x;
    if (bid < NBF) {
        // qh[bf] = q[bf] @ (W_q + W_d) + b_h
        __shared__ float ws[2304];      // [k=64][j=36] W_q+W_d
        __shared__ float qv[64];
        const int f = bid & 7;
        const float* Wf = W_h + f * (3 * ND * NH);
        for (int i = t; i < 2304; i += 256) {
            ws[i] = Wf[ND * NH + i] + Wf[2 * ND * NH + i];
        }
        if (t < 64) qv[t] = q[(size_t)bid * ND + t];
        __syncthreads();
        if (t < NH) {
            float s = b_h[f * NH + t];
            #pragma unroll 8
            for (int k = 0; k < ND; ++k)
                s = fmaf(qv[k], ws[k * NH + t], s);
            g_qh[bid * NH + t] = s;
        }
    } else {
        // A[f] in pass1 layout: [k][quarter][12], cols 9..11 zero
        const int f = bid - NBF;
        const float* Wf = W_h + f * (3 * ND * NH);
        for (int i = t; i < 3072; i += 256) {
            int k = i / 48, c = i - k * 48;
            int qq = c / 12, cc = c - qq * 12;
            float v = 0.0f;
            if (cc < 9) {
                int j = qq * 9 + cc;
                v = Wf[k * NH + j] - Wf[(2 * ND + k) * NH + j];
            }
            g_A[f * 3072 + i] = v;
        }
    }
}

// ---------------------------------------------------------------------------
// Pass 1: per-CTA 128-row tile of K_f @ A_f. h = key@A + qh (qh in acc init).
// Warp = 9-col quarter; lane = rows {l,l+32,l+64,l+96}. Stats via shfl.
// ---------------------------------------------------------------------------
__global__ void __launch_bounds__(P1T, 4) pass1_kernel(
    const float* __restrict__ key)
{
    extern __shared__ float sm[];
    float* A_s   = sm + SM_A;     // [64][48]
    float* qh_sm = sm + SM_QH;    // [2][4][10]
    float* kt    = sm + SM_KT;    // [64][129]
    float* h_st  = sm + SM_KT;    // reuse: [128][38]

    const int t = threadIdx.x;
    const int wq = t >> 5;        // warp = col quarter (cols 9*wq .. 9*wq+8)
    const int l  = t & 31;
    const int f    = blockIdx.x / NTILES;
    const int tile = blockIdx.x - f * NTILES;
    const int g0 = tile * 128;
    const int b0 = g0 / NS;

    // A: pure coalesced copy from g_A
    {
        const float4* ga = (const float4*)(g_A + f * 3072);
        float4* as4 = (float4*)A_s;
        #pragma unroll
        for (int it = 0; it < 6; ++it)
            as4[t + it * P1T] = ga[t + it * P1T];
    }
    // key tile -> transposed f32 smem (coalesced LDG.128, scalar STS)
    const float4* kg = (const float4*)key;
    #pragma unroll
    for (int it = 0; it < 16; ++it) {
        int i = t + it * P1T;            // 0..2047
        int row = i >> 4, c4 = (i & 15) * 4;
        int g = g0 + row;
        int b = g / NS, s = g - b * NS;
        float4 v = kg[((size_t)(b * NF + f) * NS + s) * 16 + (i & 15)];
        kt[(c4 + 0) * KTP + row] = v.x;
        kt[(c4 + 1) * KTP + row] = v.y;
        kt[(c4 + 2) * KTP + row] = v.z;
        kt[(c4 + 3) * KTP + row] = v.w;
    }
    // qh: 1 LDG per thread (72 threads)
    if (t < 72) {
        int bb = t / 36, j = t - bb * 36;
        int b = b0 + bb; if (b > NB - 1) b = NB - 1;
        int qq = j / 9, cc = j - qq * 9;
        qh_sm[bb * 40 + qq * 10 + cc] = g_qh[(b * NF + f) * NH + j];
    }
    __syncthreads();

    // ---- main GEMM: acc initialized with qh so h = acc at loop exit ----
    unsigned long long acc[4][4];
    float acc8[4];
    #pragma unroll
    for (int j4 = 0; j4 < 4; ++j4) {
        int bsel = ((g0 + l + 32 * j4) >= (b0 + 1) * NS) ? 1 : 0;
        const float* qh = qh_sm + bsel * 40 + wq * 10;
        #pragma unroll
        for (int c = 0; c < 4; ++c)
            acc[j4][c] = *(const unsigned long long*)(qh + 2 * c);
        acc8[j4] = qh[8];
    }

    const float* abase = A_s + wq * 12;
    const float* kbase = kt + l;
    #pragma unroll 4
    for (int k = 0; k < ND; ++k) {
        const float* ar = abase + k * 48;
        F4U2 u0; u0.f4 = *(const float4*)(ar);       // a0..a3
        F4U2 u1; u1.f4 = *(const float4*)(ar + 4);   // a4..a7
        float a8 = ar[8];
        const float* kc = kbase + k * KTP;
        float kv0 = kc[0], kv1 = kc[32], kv2 = kc[64], kv3 = kc[96];
        {
            unsigned long long kk = pack2(kv0);
            fma2(acc[0][0], u0.u2.x, kk); fma2(acc[0][1], u0.u2.y, kk);
            fma2(acc[0][2], u1.u2.x, kk); fma2(acc[0][3], u1.u2.y, kk);
            acc8[0] = fmaf(a8, kv0, acc8[0]);
        }
        {
            unsigned long long kk = pack2(kv1);
            fma2(acc[1][0], u0.u2.x, kk); fma2(acc[1][1], u0.u2.y, kk);
            fma2(acc[1][2], u1.u2.x, kk); fma2(acc[1][3], u1.u2.y, kk);
            acc8[1] = fmaf(a8, kv1, acc8[1]);
        }
        {
            unsigned long long kk = pack2(kv2);
            fma2(acc[2][0], u0.u2.x, kk); fma2(acc[2][1], u0.u2.y, kk);
            fma2(acc[2][2], u1.u2.x, kk); fma2(acc[2][3], u1.u2.y, kk);
            acc8[2] = fmaf(a8, kv2, acc8[2]);
        }
        {
            unsigned long long kk = pack2(kv3);
            fma2(acc[3][0], u0.u2.x, kk); fma2(acc[3][1], u0.u2.y, kk);
            fma2(acc[3][2], u1.u2.x, kk); fma2(acc[3][3], u1.u2.y, kk);
            acc8[3] = fmaf(a8, kv3, acc8[3]);
        }
    }
    __syncthreads();   // done reading kt -> safe to overwrite with h

    // epilogue: store h + accumulate per-column partials in registers
    const int jc = wq * 9;
    float cs[9], cq[9];
    #pragma unroll
    for (int c = 0; c < 9; ++c) { cs[c] = 0.0f; cq[c] = 0.0f; }
    #pragma unroll
    for (int j4 = 0; j4 < 4; ++j4) {
        int r = l + 32 * j4;
        float* hr = h_st + r * HPAD + jc;
        #pragma unroll
        for (int c = 0; c < 4; ++c) {
            F2U1 u; u.u = acc[j4][c];
            float h0 = u.f2.x, h1 = u.f2.y;
            hr[2 * c] = h0; hr[2 * c + 1] = h1;
            cs[2 * c]     += h0; cq[2 * c]     = fmaf(h0, h0, cq[2 * c]);
            cs[2 * c + 1] += h1; cq[2 * c + 1] = fmaf(h1, h1, cq[2 * c + 1]);
        }
        float h8 = acc8[j4];
        hr[8] = h8;
        cs[8] += h8; cq[8] = fmaf(h8, h8, cq[8]);
    }
    // warp-level reduce of 18 partials (warp owns its 9 columns completely)
    #pragma unroll
    for (int m = 16; m > 0; m >>= 1) {
        #pragma unroll
        for (int c = 0; c < 9; ++c) {
            cs[c] += __shfl_xor_sync(0xffffffffu, cs[c], m);
            cq[c] += __shfl_xor_sync(0xffffffffu, cq[c], m);
        }
    }
    if (l == 0) {
        #pragma unroll
        for (int c = 0; c < 9; ++c) {
            g_psum[blockIdx.x * NH + jc + c] = cs[c];
            g_psq [blockIdx.x * NH + jc + c] = cq[c];
        }
    }
    __syncthreads();

    // fp16 copy-out: 2304 half2 over 128 threads
    #pragma unroll
    for (int it = 0; it < 18; ++it) {
        int i = t + it * P1T;           // 0..2303
        int row = i / 18, e = i - row * 18;
        int gg = g0 + row;
        int b = gg / NS, s = gg - b * NS;
        float2 v = *(const float2*)(h_st + row * HPAD + 2 * e);
        g_h[((size_t)(b * NF + f) * NS + s) * 18 + e] = __float22half2_rn(v);
    }
}

// ---------------------------------------------------------------------------
// Stats finalize: reduce 400 tile-partials per (f,j)
// ---------------------------------------------------------------------------
__global__ void __launch_bounds__(256) kstats_kernel()
{
    __shared__ float rs[256], rq[256];
    const int col = blockIdx.x;           // f*36 + j
    const int f = col / NH, j = col - f * NH;
    const int t = threadIdx.x;
    float ss = 0.f, qq = 0.f;
    for (int i = t; i < NTILES; i += 256) {
        ss += g_psum[(f * NTILES + i) * NH + j];
        qq += g_psq [(f * NTILES + i) * NH + j];
    }
    rs[t] = ss; rq[t] = qq;
    __syncthreads();
    for (int off = 128; off > 0; off >>= 1) {
        if (t < off) { rs[t] += rs[t + off]; rq[t] += rq[t + off]; }
        __syncthreads();
    }
    if (t == 0) {
        const float invN = 1.0f / (float)(NB * NS);
        float mean = rs[0] * invN;
        float var  = rq[0] * invN - mean * mean;
        g_mean[col] = mean;
        g_inv[col]  = rsqrtf(var + EPS_V);
    }
}

// ---------------------------------------------------------------------------
// Pass 3: gate + scores + masked softmax + attn @ key. One block per (b,f).
// ---------------------------------------------------------------------------
__global__ void __launch_bounds__(256) pass3_kernel(
    const float* __restrict__ key, const float* __restrict__ alpha,
    const float* __restrict__ W_o, const float* __restrict__ b_o,
    const int* __restrict__ seqnum, float* __restrict__ out)
{
    __shared__ float h_sm[NS * NH];
    __shared__ float inv_s[NH], nm_s[NH], wo_s[NH];
    __shared__ float sc[NS];
    __shared__ float red[256];
    __shared__ float opart[256];

    const int tid = threadIdx.x;
    const int bf  = blockIdx.x;
    const int f   = bf & 7;
    const int n   = seqnum[bf];

    {
        const __half2* hg = g_h + (size_t)bf * (NS * NH / 2);
        for (int i = tid; i < NS * NH / 2; i += 256)
            ((float2*)h_sm)[i] = __half22float2(hg[i]);
    }
    if (tid < NH) {
        float m  = g_mean[f * NH + tid];
        float iv = g_inv [f * NH + tid];
        inv_s[tid] = iv;
        nm_s[tid]  = -m * iv;
        wo_s[tid]  = W_o[f * NH + tid];
    }
    const float al  = alpha[f];
    const float oma = 1.0f - al;
    __syncthreads();

    float score = -3.0e38f;
    if (tid < n) {
        float s = b_o[f];
        const float* hr = h_sm + tid * NH;
        #pragma unroll 6
        for (int j = 0; j < NH; ++j) {
            float v = hr[j];
            float z = fmaf(v, inv_s[j], nm_s[j]);
            float p = fast_sigmoid(z);
            float g = fmaf(oma, p, al) * v;
            s = fmaf(g, wo_s[j], s);
        }
        score = s;
    }
    red[tid] = score;
    __syncthreads();
    for (int off = 128; off > 0; off >>= 1) {
        if (tid < off) red[tid] = fmaxf(red[tid], red[tid + off]);
        __syncthreads();
    }
    const float mx = red[0];
    __syncthreads();
    float e = 0.0f;
    if (tid < n) {
        e = __expf(score - mx);
        sc[tid] = e;
    }
    red[tid] = e;
    __syncthreads();
    for (int off = 128; off > 0; off >>= 1) {
        if (tid < off) red[tid] += red[tid + off];
        __syncthreads();
    }
    const float denom = red[0];

    const int d = tid & 63;
    const int g = tid >> 6;
    const float* kb = key + (size_t)bf * (NS * ND);
    float a0 = 0.0f;
    for (int s = g; s < n; s += 4)
        a0 = fmaf(sc[s], kb[s * ND + d], a0);
    opart[tid] = a0;
    __syncthreads();
    if (tid < ND) {
        float o = opart[tid] + opart[tid + 64] + opart[tid + 128] + opart[tid + 192];
        out[(size_t)bf * ND + tid] = o / denom;
    }
}

// ---------------------------------------------------------------------------
extern "C" void kernel_launch(void* const* d_in, const int* in_sizes, int n_in,
                              void* d_out, int out_size)
{
    const float* q      = (const float*)d_in[0];
    const float* key    = (const float*)d_in[1];
    const float* W_h    = (const float*)d_in[2];
    const float* b_h    = (const float*)d_in[3];
    const float* alpha  = (const float*)d_in[4];
    const float* W_o    = (const float*)d_in[5];
    const float* b_o    = (const float*)d_in[6];
    const int*   seqn   = (const int*)d_in[7];
    float* out = (float*)d_out;

    cudaFuncSetAttribute(pass1_kernel,
                         cudaFuncAttributeMaxDynamicSharedMemorySize,
                         P1_SMEM_BYTES);

    prep_kernel<<<NBF + NF, 256>>>(q, W_h, b_h);
    pass1_kernel<<<P1GRID, P1T, P1_SMEM_BYTES>>>(key);
    kstats_kernel<<<NSTAT, 256>>>();
    pass3_kernel<<<NBF, 256>>>(key, alpha, W_o, b_o, seqn, out);
}

// round 13
// speedup vs baseline: 1.1708x; 1.0773x over previous
#include <cuda_runtime.h>
#include <cuda_fp16.h>
#include <cstdint>

// Shapes
#define NB 256
#define NF 8
#define NS 200
#define ND 64
#define NH 36
#define NBF (NB*NF)          // 2048
#define NSTAT (NF*NH)        // 288
#define EPS_V 1e-3f

#define NTILES 400           // tiles of 128 rows over NB*NS=51200 rows per f
#define P1T 128
#define P1GRID (NF*NTILES)   // 3200

// ---- pass1 shared memory (float indices) ----
// A_s:   [0,3072)       [k=64][quarter=4][12] (cols 9..11 zero)
// qh_s:  [3072,3152)    [2][4 quarters][10]
// kt:    [3200,7328)    key f32 transposed CHUNK [32][129]
// h_st:  overlays [0,4864)  h staging [128][38] (A/qh/kt dead by then)
#define SM_A 0
#define SM_QH 3072
#define SM_KT 3200
#define KTP 129
#define KCH 32                // k-chunk
#define HPAD 38
#define P1_SMEM_FLOATS 7328
#define P1_SMEM_BYTES  (P1_SMEM_FLOATS*4)          // 29312

// Scratch (no allocs -> device globals)
__device__ __half2 g_h[(size_t)NBF * (NS * NH / 2)];   // fp16 hidden acts
__device__ float g_A  [NF * 3072];                     // prepped A, pass1 layout
__device__ float g_qh [NBF * NH];                      // prepped qh
__device__ float g_psum[P1GRID * NH];
__device__ float g_psq [P1GRID * NH];
__device__ float g_mean[NSTAT];
__device__ float g_inv [NSTAT];

union F4U2 { float4 f4; ulonglong2 u2; };
union F2U1 { float2 f2; unsigned long long u; };

__device__ __forceinline__ unsigned long long pack2(float x) {
    unsigned long long r;
    asm("mov.b64 %0, {%1, %1};" : "=l"(r) : "f"(x));
    return r;
}
__device__ __forceinline__ void fma2(unsigned long long &acc,
                                     unsigned long long a,
                                     unsigned long long b) {
    asm("fma.rn.f32x2 %0, %1, %2, %0;" : "+l"(acc) : "l"(a), "l"(b));
}

// FFMA-only sigmoid (no MUFU pressure)
__device__ __forceinline__ float fast_sigmoid(float z) {
    float x = -z * 1.4426950408889634f;
    x = fminf(fmaxf(x, -30.0f), 30.0f);
    float n = rintf(x);
    float fr = x - n;
    float p = 0.0013333558f;
    p = fmaf(p, fr, 0.009618129f);
    p = fmaf(p, fr, 0.055504109f);
    p = fmaf(p, fr, 0.24022651f);
    p = fmaf(p, fr, 0.69314718f);
    p = fmaf(p, fr, 1.0f);
    float sc = __int_as_float(((int)n + 127) << 23);
    float e = p * sc;                 // exp(-z)
    float w = 1.0f + e;
    float r = __int_as_float(0x7EF311C3 - __float_as_int(w));
    r = r * (2.0f - w * r);
    r = r * (2.0f - w * r);
    return r;
}

// ---------------------------------------------------------------------------
// Prep: A (per f) and qh (per b,f) computed ONCE.
// ---------------------------------------------------------------------------
__global__ void __launch_bounds__(256) prep_kernel(
    const float* __restrict__ q, const float* __restrict__ W_h,
    const float* __restrict__ b_h)
{
    const int bid = blockIdx.x;
    const int t = threadIdx.x;
    if (bid < NBF) {
        __shared__ float ws[2304];      // [k=64][j=36] W_q+W_d
        __shared__ float qv[64];
        const int f = bid & 7;
        const float* Wf = W_h + f * (3 * ND * NH);
        for (int i = t; i < 2304; i += 256)
            ws[i] = Wf[ND * NH + i] + Wf[2 * ND * NH + i];
        if (t < 64) qv[t] = q[(size_t)bid * ND + t];
        __syncthreads();
        if (t < NH) {
            float s = b_h[f * NH + t];
            #pragma unroll 8
            for (int k = 0; k < ND; ++k)
                s = fmaf(qv[k], ws[k * NH + t], s);
            g_qh[bid * NH + t] = s;
        }
    } else {
        const int f = bid - NBF;
        const float* Wf = W_h + f * (3 * ND * NH);
        for (int i = t; i < 3072; i += 256) {
            int k = i / 48, c = i - k * 48;
            int qq = c / 12, cc = c - qq * 12;
            float v = 0.0f;
            if (cc < 9) {
                int j = qq * 9 + cc;
                v = Wf[k * NH + j] - Wf[(2 * ND + k) * NH + j];
            }
            g_A[f * 3072 + i] = v;
        }
    }
}

// ---------------------------------------------------------------------------
// Pass 1: per-CTA 128-row tile of K_f @ A_f, K processed in 2 chunks of 32
// (single 16.6KB kt buffer -> 29.3KB smem -> 6 CTAs/SM).
// Warp = 9-col quarter; lane = rows {l,l+32,l+64,l+96}. Stats via shfl.
// ---------------------------------------------------------------------------
__global__ void __launch_bounds__(P1T, 6) pass1_kernel(
    const float* __restrict__ key)
{
    extern __shared__ float sm[];
    float* A_s   = sm + SM_A;     // [64][48]
    float* qh_sm = sm + SM_QH;    // [2][4][10]
    float* kt    = sm + SM_KT;    // [32][129] chunk
    float* h_st  = sm;            // reuse: [128][38]

    const int t = threadIdx.x;
    const int wq = t >> 5;        // warp = col quarter (cols 9*wq .. 9*wq+8)
    const int l  = t & 31;
    const int f    = blockIdx.x / NTILES;
    const int tile = blockIdx.x - f * NTILES;
    const int g0 = tile * 128;
    const int b0 = g0 / NS;
    const float4* kg = (const float4*)key;

    // A: coalesced copy from g_A
    {
        const float4* ga = (const float4*)(g_A + f * 3072);
        float4* as4 = (float4*)A_s;
        #pragma unroll
        for (int it = 0; it < 6; ++it)
            as4[t + it * P1T] = ga[t + it * P1T];
    }
    // qh: 1 LDG per thread (72 threads)
    if (t < 72) {
        int bb = t / 36, j = t - bb * 36;
        int b = b0 + bb; if (b > NB - 1) b = NB - 1;
        int qq = j / 9, cc = j - qq * 9;
        qh_sm[bb * 40 + qq * 10 + cc] = g_qh[(b * NF + f) * NH + j];
    }
    // key chunk 0 -> transposed smem
    #pragma unroll
    for (int it = 0; it < 8; ++it) {
        int i = t + it * P1T;            // 0..1023
        int row = i >> 3, c4 = i & 7;    // 8 float4 per row in a chunk
        int g = g0 + row;
        int b = g / NS, s = g - b * NS;
        float4 v = kg[((size_t)(b * NF + f) * NS + s) * 16 + c4];
        kt[(c4 * 4 + 0) * KTP + row] = v.x;
        kt[(c4 * 4 + 1) * KTP + row] = v.y;
        kt[(c4 * 4 + 2) * KTP + row] = v.z;
        kt[(c4 * 4 + 3) * KTP + row] = v.w;
    }
    __syncthreads();

    // acc init with qh
    unsigned long long acc[4][4];
    float acc8[4];
    #pragma unroll
    for (int j4 = 0; j4 < 4; ++j4) {
        int bsel = ((g0 + l + 32 * j4) >= (b0 + 1) * NS) ? 1 : 0;
        const float* qh = qh_sm + bsel * 40 + wq * 10;
        #pragma unroll
        for (int c = 0; c < 4; ++c)
            acc[j4][c] = *(const unsigned long long*)(qh + 2 * c);
        acc8[j4] = qh[8];
    }

    const float* abase = A_s + wq * 12;
    const float* kbase = kt + l;

    #pragma unroll
    for (int ch = 0; ch < 2; ++ch) {
        if (ch == 1) {
            __syncthreads();   // chunk0 fma done
            #pragma unroll
            for (int it = 0; it < 8; ++it) {
                int i = t + it * P1T;
                int row = i >> 3, c4 = i & 7;
                int g = g0 + row;
                int b = g / NS, s = g - b * NS;
                float4 v = kg[((size_t)(b * NF + f) * NS + s) * 16 + 8 + c4];
                kt[(c4 * 4 + 0) * KTP + row] = v.x;
                kt[(c4 * 4 + 1) * KTP + row] = v.y;
                kt[(c4 * 4 + 2) * KTP + row] = v.z;
                kt[(c4 * 4 + 3) * KTP + row] = v.w;
            }
            __syncthreads();
        }
        const float* ach = abase + ch * KCH * 48;
        #pragma unroll 4
        for (int kl = 0; kl < KCH; ++kl) {
            const float* ar = ach + kl * 48;
            F4U2 u0; u0.f4 = *(const float4*)(ar);       // a0..a3
            F4U2 u1; u1.f4 = *(const float4*)(ar + 4);   // a4..a7
            float a8 = ar[8];
            const float* kc = kbase + kl * KTP;
            float kv0 = kc[0], kv1 = kc[32], kv2 = kc[64], kv3 = kc[96];
            {
                unsigned long long kk = pack2(kv0);
                fma2(acc[0][0], u0.u2.x, kk); fma2(acc[0][1], u0.u2.y, kk);
                fma2(acc[0][2], u1.u2.x, kk); fma2(acc[0][3], u1.u2.y, kk);
                acc8[0] = fmaf(a8, kv0, acc8[0]);
            }
            {
                unsigned long long kk = pack2(kv1);
                fma2(acc[1][0], u0.u2.x, kk); fma2(acc[1][1], u0.u2.y, kk);
                fma2(acc[1][2], u1.u2.x, kk); fma2(acc[1][3], u1.u2.y, kk);
                acc8[1] = fmaf(a8, kv1, acc8[1]);
            }
            {
                unsigned long long kk = pack2(kv2);
                fma2(acc[2][0], u0.u2.x, kk); fma2(acc[2][1], u0.u2.y, kk);
                fma2(acc[2][2], u1.u2.x, kk); fma2(acc[2][3], u1.u2.y, kk);
                acc8[2] = fmaf(a8, kv2, acc8[2]);
            }
            {
                unsigned long long kk = pack2(kv3);
                fma2(acc[3][0], u0.u2.x, kk); fma2(acc[3][1], u0.u2.y, kk);
                fma2(acc[3][2], u1.u2.x, kk); fma2(acc[3][3], u1.u2.y, kk);
                acc8[3] = fmaf(a8, kv3, acc8[3]);
            }
        }
    }
    __syncthreads();   // all fma done -> safe to overlay h_st

    // epilogue: store h + per-column partials in registers
    const int jc = wq * 9;
    float cs[9], cq[9];
    #pragma unroll
    for (int c = 0; c < 9; ++c) { cs[c] = 0.0f; cq[c] = 0.0f; }
    #pragma unroll
    for (int j4 = 0; j4 < 4; ++j4) {
        int r = l + 32 * j4;
        float* hr = h_st + r * HPAD + jc;
        #pragma unroll
        for (int c = 0; c < 4; ++c) {
            F2U1 u; u.u = acc[j4][c];
            float h0 = u.f2.x, h1 = u.f2.y;
            hr[2 * c] = h0; hr[2 * c + 1] = h1;
            cs[2 * c]     += h0; cq[2 * c]     = fmaf(h0, h0, cq[2 * c]);
            cs[2 * c + 1] += h1; cq[2 * c + 1] = fmaf(h1, h1, cq[2 * c + 1]);
        }
        float h8 = acc8[j4];
        hr[8] = h8;
        cs[8] += h8; cq[8] = fmaf(h8, h8, cq[8]);
    }
    #pragma unroll
    for (int m = 16; m > 0; m >>= 1) {
        #pragma unroll
        for (int c = 0; c < 9; ++c) {
            cs[c] += __shfl_xor_sync(0xffffffffu, cs[c], m);
            cq[c] += __shfl_xor_sync(0xffffffffu, cq[c], m);
        }
    }
    if (l == 0) {
        #pragma unroll
        for (int c = 0; c < 9; ++c) {
            g_psum[blockIdx.x * NH + jc + c] = cs[c];
            g_psq [blockIdx.x * NH + jc + c] = cq[c];
        }
    }
    __syncthreads();

    // fp16 copy-out: 2304 half2 over 128 threads
    #pragma unroll
    for (int it = 0; it < 18; ++it) {
        int i = t + it * P1T;           // 0..2303
        int row = i / 18, e = i - row * 18;
        int gg = g0 + row;
        int b = gg / NS, s = gg - b * NS;
        float2 v = *(const float2*)(h_st + row * HPAD + 2 * e);
        g_h[((size_t)(b * NF + f) * NS + s) * 18 + e] = __float22half2_rn(v);
    }
}

// ---------------------------------------------------------------------------
// Stats finalize: reduce 400 tile-partials per (f,j)
// ---------------------------------------------------------------------------
__global__ void __launch_bounds__(256) kstats_kernel()
{
    __shared__ float rs[256], rq[256];
    const int col = blockIdx.x;           // f*36 + j
    const int f = col / NH, j = col - f * NH;
    const int t = threadIdx.x;
    float ss = 0.f, qq = 0.f;
    for (int i = t; i < NTILES; i += 256) {
        ss += g_psum[(f * NTILES + i) * NH + j];
        qq += g_psq [(f * NTILES + i) * NH + j];
    }
    rs[t] = ss; rq[t] = qq;
    __syncthreads();
    for (int off = 128; off > 0; off >>= 1) {
        if (t < off) { rs[t] += rs[t + off]; rq[t] += rq[t + off]; }
        __syncthreads();
    }
    if (t == 0) {
        const float invN = 1.0f / (float)(NB * NS);
        float mean = rs[0] * invN;
        float var  = rq[0] * invN - mean * mean;
        g_mean[col] = mean;
        g_inv[col]  = rsqrtf(var + EPS_V);
    }
}

// ---------------------------------------------------------------------------
// Pass 3: gate + scores + masked softmax + attn @ key.
// h load bounded by seqnum; shfl-based reductions (4 barriers total).
// ---------------------------------------------------------------------------
__global__ void __launch_bounds__(256) pass3_kernel(
    const float* __restrict__ key, const float* __restrict__ alpha,
    const float* __restrict__ W_o, const float* __restrict__ b_o,
    const int* __restrict__ seqnum, float* __restrict__ out)
{
    __shared__ float h_sm[NS * NH];
    __shared__ float inv_s[NH], nm_s[NH], wo_s[NH];
    __shared__ float sc[NS];
    __shared__ float red[16];
    __shared__ float opart[256];

    const int tid = threadIdx.x;
    const int wid = tid >> 5, lid = tid & 31;
    const int bf  = blockIdx.x;
    const int f   = bf & 7;
    const int n   = seqnum[bf];

    {
        const __half2* hg = g_h + (size_t)bf * (NS * NH / 2);
        const int tot = n * 18;      // only live rows
        for (int i = tid; i < tot; i += 256)
            ((float2*)h_sm)[i] = __half22float2(hg[i]);
    }
    if (tid < NH) {
        float m  = g_mean[f * NH + tid];
        float iv = g_inv [f * NH + tid];
        inv_s[tid] = iv;
        nm_s[tid]  = -m * iv;
        wo_s[tid]  = W_o[f * NH + tid];
    }
    const float al  = alpha[f];
    const float oma = 1.0f - al;
    __syncthreads();

    float score = -3.0e38f;
    if (tid < n) {
        float s = b_o[f];
        const float* hr = h_sm + tid * NH;
        #pragma unroll 6
        for (int j = 0; j < NH; ++j) {
            float v = hr[j];
            float z = fmaf(v, inv_s[j], nm_s[j]);
            float p = fast_sigmoid(z);
            float g = fmaf(oma, p, al) * v;
            s = fmaf(g, wo_s[j], s);
        }
        score = s;
    }
    // warp max -> 8 partials -> local max
    float mv = score;
    #pragma unroll
    for (int m = 16; m > 0; m >>= 1)
        mv = fmaxf(mv, __shfl_xor_sync(0xffffffffu, mv, m));
    if (lid == 0) red[wid] = mv;
    __syncthreads();
    float mx = red[0];
    #pragma unroll
    for (int w = 1; w < 8; ++w) mx = fmaxf(mx, red[w]);

    float e = 0.0f;
    if (tid < n) {
        e = __expf(score - mx);
        sc[tid] = e;
    }
    float sv = e;
    #pragma unroll
    for (int m = 16; m > 0; m >>= 1)
        sv += __shfl_xor_sync(0xffffffffu, sv, m);
    if (lid == 0) red[8 + wid] = sv;
    __syncthreads();   // also publishes sc[]
    float denom = red[8];
    #pragma unroll
    for (int w = 1; w < 8; ++w) denom += red[8 + w];

    const int d = tid & 63;
    const int g = tid >> 6;
    const float* kb = key + (size_t)bf * (NS * ND);
    float a0 = 0.0f;
    for (int s = g; s < n; s += 4)
        a0 = fmaf(sc[s], kb[s * ND + d], a0);
    opart[tid] = a0;
    __syncthreads();
    if (tid < ND) {
        float o = opart[tid] + opart[tid + 64] + opart[tid + 128] + opart[tid + 192];
        out[(size_t)bf * ND + tid] = o / denom;
    }
}

// ---------------------------------------------------------------------------
extern "C" void kernel_launch(void* const* d_in, const int* in_sizes, int n_in,
                              void* d_out, int out_size)
{
    const float* q      = (const float*)d_in[0];
    const float* key    = (const float*)d_in[1];
    const float* W_h    = (const float*)d_in[2];
    const float* b_h    = (const float*)d_in[3];
    const float* alpha  = (const float*)d_in[4];
    const float* W_o    = (const float*)d_in[5];
    const float* b_o    = (const float*)d_in[6];
    const int*   seqn   = (const int*)d_in[7];
    float* out = (float*)d_out;

    cudaFuncSetAttribute(pass1_kernel,
                         cudaFuncAttributeMaxDynamicSharedMemorySize,
                         P1_SMEM_BYTES);

    prep_kernel<<<NBF + NF, 256>>>(q, W_h, b_h);
    pass1_kernel<<<P1GRID, P1T, P1_SMEM_BYTES>>>(key);
    kstats_kernel<<<NSTAT, 256>>>();
    pass3_kernel<<<NBF, 256>>>(key, alpha, W_o, b_o, seqn, out);
}